// round 1
// baseline (speedup 1.0000x reference)
#include <cuda_runtime.h>

#define BATCH 32768
#define NODES 1024
#define NC 24
#define WARPS_PB 8
#define THREADS (WARPS_PB * 32)
#define GRID 2048
#define ROWS_PER_WARP (BATCH / (GRID * WARPS_PB))  // 2

__device__ float g_partial[GRID];

__global__ __launch_bounds__(THREADS) void tree_loss_main(
    const float* __restrict__ fs, const int* __restrict__ labels)
{
    __shared__ float s_coarse[WARPS_PB][NC];
    __shared__ float s_acc[WARPS_PB];
    const int warp = threadIdx.x >> 5;
    const int lane = threadIdx.x & 31;
    const int gwarp = blockIdx.x * WARPS_PB + warp;
    float acc = 0.f;

    for (int r = 0; r < ROWS_PER_WARP; ++r) {
        const int row = gwarp * ROWS_PER_WARP + r;
        const float* __restrict__ fr = fs + (size_t)row * NODES;

        // coarse (parent) values for this row -> shared
        if (lane < NC) s_coarse[warp][lane] = fr[lane];
        __syncwarp();
        const float* C = s_coarse[warp];

        const int label = labels[row];             // broadcast load
        const bool coarseLabel = (label < NC);

        // 8 coalesced float4 loads: iteration i covers a contiguous 512B
        // stripe across the warp; all 8 issued up front (MLP = 8).
        float4 v[8];
        const float4* __restrict__ fp = reinterpret_cast<const float4*>(fr);
        #pragma unroll
        for (int i = 0; i < 8; ++i) v[i] = fp[i * 32 + lane];

        float zsum = 0.f, msum = 0.f;
        // q tracks nn % 24 incrementally; nn = 128*i + 4*lane + j
        int q = (4 * lane) % NC;

        #pragma unroll
        for (int i = 0; i < 8; ++i) {
            float xv[4] = { v[i].x, v[i].y, v[i].z, v[i].w };
            #pragma unroll
            for (int j = 0; j < 4; ++j) {
                const int nn = 128 * i + 4 * lane + j;
                // for i>=1, nn >= 128 > 24 is provable -> predicate folds away
                const float parent = (nn >= NC) ? C[q] : 0.f;
                const float t = __expf(xv[j] + parent);
                zsum += t;
                if (coarseLabel) {  // warp-uniform, ~2.3% of rows
                    const bool sel = (nn == label) | ((nn >= NC) & (q == label));
                    if (sel) msum += t;
                }
                q = (q + 1 >= NC) ? (q + 1 - NC) : (q + 1);   // +1 per j
            }
            q = (q + 4 >= NC) ? (q + 4 - NC) : (q + 4);       // total +8 per i (128 % 24)
        }

        // warp reductions
        #pragma unroll
        for (int off = 16; off; off >>= 1) {
            zsum += __shfl_xor_sync(0xffffffffu, zsum, off);
            msum += __shfl_xor_sync(0xffffffffu, msum, off);
        }

        if (lane == 0) {
            float marg;
            if (coarseLabel) {
                marg = msum;
            } else {
                // fine label: single pair term, parent index = label % 24
                marg = __expf(fr[label] + C[label % NC]);
            }
            acc += __logf(1.f + zsum) - __logf(marg);
        }
        __syncwarp();  // order last C[] reads before next row's rewrite
    }

    if (lane == 0) s_acc[warp] = acc;
    __syncthreads();
    if (threadIdx.x == 0) {
        float s = 0.f;
        #pragma unroll
        for (int w = 0; w < WARPS_PB; ++w) s += s_acc[w];
        g_partial[blockIdx.x] = s;
    }
}

__global__ __launch_bounds__(1024) void tree_loss_reduce(float* __restrict__ out)
{
    __shared__ float sh[1024];
    const int t = threadIdx.x;
    sh[t] = g_partial[t] + g_partial[t + 1024];
    __syncthreads();
    #pragma unroll
    for (int off = 512; off; off >>= 1) {
        if (t < off) sh[t] += sh[t + off];
        __syncthreads();
    }
    if (t == 0) out[0] = sh[0] * (1.0f / (float)BATCH);
}

extern "C" void kernel_launch(void* const* d_in, const int* in_sizes, int n_in,
                              void* d_out, int out_size)
{
    const float* fs     = (const float*)d_in[0];
    const int*   labels = (const int*)d_in[1];
    // d_in[2] = stateSpace: structure is compile-time known, unused.
    tree_loss_main<<<GRID, THREADS>>>(fs, labels);
    tree_loss_reduce<<<1, 1024>>>((float*)d_out);
}

// round 2
// speedup vs baseline: 1.3571x; 1.3571x over previous
#include <cuda_runtime.h>
#include <cstdint>

#define BATCH 32768
#define NODES 1024
#define NC 24
#define WARPS_PB 4
#define THREADS (WARPS_PB * 32)   // 128
#define GRID 4096
#define RPW 2                     // rows per warp: 32768 / (4096*4)

__device__ float    g_partial[GRID];
__device__ unsigned g_count = 0;  // self-resetting ticket (graph-replay safe)

__device__ __forceinline__ void cp_async16(uint32_t dst_smem, const float* src) {
    asm volatile("cp.async.cg.shared.global [%0], [%1], 16;\n"
                 :: "r"(dst_smem), "l"(src));
}

// Full loss for one row whose 1024 floats sit in `buf` (shared). All lanes
// return the identical value (shfl-xor reduction broadcasts the sums).
__device__ __forceinline__ float row_loss(const float* __restrict__ buf,
                                          int label, int lane)
{
    const float4* __restrict__ b4 = reinterpret_cast<const float4*>(buf);
    float4 v[8];
    #pragma unroll
    for (int i = 0; i < 8; ++i) v[i] = b4[i * 32 + lane];   // conflict-free

    const bool coarse = (label < NC);
    float zsum = 0.f, msum = 0.f;
    int q = (4 * lane) % NC;                 // q == nn % 24, nn = 128*i + 4*lane + j

    #pragma unroll
    for (int i = 0; i < 8; ++i) {
        float xv[4] = { v[i].x, v[i].y, v[i].z, v[i].w };
        #pragma unroll
        for (int j = 0; j < 4; ++j) {
            const int nn = 128 * i + 4 * lane + j;
            const float parent = (nn >= NC) ? buf[q] : 0.f;  // folds for i>=1
            const float t = __expf(xv[j] + parent);
            zsum += t;
            if (coarse) {                    // warp-uniform, ~2.3% of rows
                const bool sel = (nn == label) | ((nn >= NC) & (q == label));
                if (sel) msum += t;
            }
            q = (q + 1 >= NC) ? (q + 1 - NC) : (q + 1);
        }
        q = (q + 4 >= NC) ? (q + 4 - NC) : (q + 4);          // 128 % 24 == 8 total
    }

    #pragma unroll
    for (int off = 16; off; off >>= 1) {
        zsum += __shfl_xor_sync(0xffffffffu, zsum, off);
        msum += __shfl_xor_sync(0xffffffffu, msum, off);
    }

    const float marg = coarse ? msum : __expf(buf[label] + buf[label % NC]);
    return __logf(1.f + zsum) - __logf(marg);
}

__global__ __launch_bounds__(THREADS) void tree_loss_fused(
    const float* __restrict__ fs, const int* __restrict__ labels,
    float* __restrict__ out)
{
    __shared__ float    sbuf[RPW][WARPS_PB][NODES];   // 32 KB
    __shared__ float    s_acc[WARPS_PB];
    __shared__ float    s_red[THREADS];
    __shared__ unsigned s_ticket;

    const int warp  = threadIdx.x >> 5;
    const int lane  = threadIdx.x & 31;
    const int gwarp = blockIdx.x * WARPS_PB + warp;
    const int row0  = gwarp * RPW;

    // Prefetch both rows: 16 cp.async of 16B per lane = 8KB in flight / warp,
    // no register cost. One commit group per row.
    #pragma unroll
    for (int r = 0; r < RPW; ++r) {
        const float* src = fs + (size_t)(row0 + r) * NODES;
        uint32_t dst = (uint32_t)__cvta_generic_to_shared(&sbuf[r][warp][0]);
        #pragma unroll
        for (int i = 0; i < 8; ++i) {
            const int off = (i * 32 + lane) * 4;     // float index, coalesced
            cp_async16(dst + off * 4, src + off);
        }
        asm volatile("cp.async.commit_group;");
    }

    const int lab0 = labels[row0];
    const int lab1 = labels[row0 + 1];

    float acc;
    asm volatile("cp.async.wait_group 1;" ::: "memory");
    __syncwarp();
    acc  = row_loss(sbuf[0][warp], lab0, lane);
    asm volatile("cp.async.wait_group 0;" ::: "memory");
    __syncwarp();
    acc += row_loss(sbuf[1][warp], lab1, lane);

    if (lane == 0) s_acc[warp] = acc;
    __syncthreads();

    if (threadIdx.x == 0) {
        float s = s_acc[0] + s_acc[1] + s_acc[2] + s_acc[3];
        g_partial[blockIdx.x] = s;
        __threadfence();
        s_ticket = atomicAdd(&g_count, 1u);
    }
    __syncthreads();

    // Last block performs the (deterministic, fixed-order) final sum.
    if (s_ticket == GRID - 1) {
        float s = 0.f;
        #pragma unroll 4
        for (int k = threadIdx.x; k < GRID; k += THREADS) s += g_partial[k];
        s_red[threadIdx.x] = s;
        __syncthreads();
        #pragma unroll
        for (int off = THREADS / 2; off; off >>= 1) {
            if (threadIdx.x < off) s_red[threadIdx.x] += s_red[threadIdx.x + off];
            __syncthreads();
        }
        if (threadIdx.x == 0) {
            out[0] = s_red[0] * (1.0f / (float)BATCH);
            g_count = 0;                      // reset for next graph replay
        }
    }
}

extern "C" void kernel_launch(void* const* d_in, const int* in_sizes, int n_in,
                              void* d_out, int out_size)
{
    const float* fs     = (const float*)d_in[0];
    const int*   labels = (const int*)d_in[1];
    // d_in[2] = stateSpace: compile-time-known structure, unused.
    tree_loss_fused<<<GRID, THREADS>>>(fs, labels, (float*)d_out);
}

// round 3
// speedup vs baseline: 1.3767x; 1.0144x over previous
#include <cuda_runtime.h>
#include <cstdint>

#define BATCH 32768
#define NODES 1024
#define NC 24
#define WARPS_PB 4
#define THREADS (WARPS_PB * 32)   // 128
#define GRID 4096
#define RPW 2                     // rows per warp
#define L2E 1.4426950408889634f
#define LN2 0.6931471805599453f

__device__ float    g_partial[GRID];
__device__ unsigned g_count = 0;  // self-resetting ticket (graph-replay safe)

__device__ __forceinline__ void cp_async16(uint32_t dst_smem, const float* src) {
    asm volatile("cp.async.cg.shared.global [%0], [%1], 16;\n"
                 :: "r"(dst_smem), "l"(src));
}
__device__ __forceinline__ float ex2(float x) {
    float r; asm("ex2.approx.ftz.f32 %0, %1;" : "=f"(r) : "f"(x)); return r;
}
__device__ __forceinline__ float lg2(float x) {
    float r; asm("lg2.approx.ftz.f32 %0, %1;" : "=f"(r) : "f"(x)); return r;
}

// Loss for one row resident in shared `buf` (1024 floats); `pp` = wrap-padded
// parent array: pp[k] = buf[k<24 ? k : k-24] * log2e, k < 28.
__device__ __forceinline__ float row_loss(const float* __restrict__ buf,
                                          const float* __restrict__ pp,
                                          int label, int lane)
{
    const float4* __restrict__ b4 = reinterpret_cast<const float4*>(buf);
    float4 v[8];
    #pragma unroll
    for (int i = 0; i < 8; ++i) v[i] = b4[i * 32 + lane];   // conflict-free

    // parent bases: base_i = (4*lane + 8i) % 24, period 3 in i
    int b0 = (4 * lane) % 24;
    int b1 = b0 + 8;  if (b1 >= 24) b1 -= 24;
    int b2 = b1 + 8;  if (b2 >= 24) b2 -= 24;
    float p[3][4];
    #pragma unroll
    for (int j = 0; j < 4; ++j) {           // distinct words -> broadcast, N=1
        p[0][j] = pp[b0 + j];
        p[1][j] = pp[b1 + j];
        p[2][j] = pp[b2 + j];
    }

    float z0 = 0.f, z1 = 0.f, z2 = 0.f, z3 = 0.f;
    #pragma unroll
    for (int i = 0; i < 8; ++i) {
        const int pi = i % 3;               // compile-time after unroll
        float xv[4] = { v[i].x, v[i].y, v[i].z, v[i].w };
        float t0, t1, t2, t3;
        if (i == 0) {                       // nn = 4*lane+j; lanes 0..5 have nn<24
            const bool noPar = (lane < 6);
            t0 = ex2(__fmaf_rn(xv[0], L2E, noPar ? 0.f : p[0][0]));
            t1 = ex2(__fmaf_rn(xv[1], L2E, noPar ? 0.f : p[0][1]));
            t2 = ex2(__fmaf_rn(xv[2], L2E, noPar ? 0.f : p[0][2]));
            t3 = ex2(__fmaf_rn(xv[3], L2E, noPar ? 0.f : p[0][3]));
        } else {
            t0 = ex2(__fmaf_rn(xv[0], L2E, p[pi][0]));
            t1 = ex2(__fmaf_rn(xv[1], L2E, p[pi][1]));
            t2 = ex2(__fmaf_rn(xv[2], L2E, p[pi][2]));
            t3 = ex2(__fmaf_rn(xv[3], L2E, p[pi][3]));
        }
        z0 += t0; z1 += t1; z2 += t2; z3 += t3;
    }
    float zsum = (z0 + z1) + (z2 + z3);
    #pragma unroll
    for (int off = 16; off; off >>= 1)
        zsum += __shfl_xor_sync(0xffffffffu, zsum, off);

    float marg;
    if (label < NC) {                       // warp-uniform rare path (~2.3%)
        // marg = E_c * (1 + S_c),  S_c = sum over fine n = label + 24m, m>=1
        const int mmax = (1023 - label) / 24;   // 41 or 42
        float S = 0.f;
        int m = lane + 1;
        if (m <= mmax) S += ex2(buf[label + 24 * m] * L2E);
        m = lane + 33;
        if (m <= mmax) S += ex2(buf[label + 24 * m] * L2E);
        #pragma unroll
        for (int off = 16; off; off >>= 1)
            S += __shfl_xor_sync(0xffffffffu, S, off);
        marg = ex2(pp[label]) * (1.f + S);
    } else {
        marg = ex2(__fmaf_rn(buf[label], L2E, pp[label % NC]));
    }
    return (lg2(1.f + zsum) - lg2(marg)) * LN2;
}

__global__ __launch_bounds__(THREADS) void tree_loss_fused(
    const float* __restrict__ fs, const int* __restrict__ labels,
    float* __restrict__ out)
{
    __shared__ float    sbuf[RPW][WARPS_PB][NODES];   // 32 KB
    __shared__ float    s_pp[RPW][WARPS_PB][28];
    __shared__ float    s_acc[WARPS_PB];
    __shared__ float    s_red[THREADS];
    __shared__ unsigned s_ticket;

    const int warp  = threadIdx.x >> 5;
    const int lane  = threadIdx.x & 31;
    const int gwarp = blockIdx.x * WARPS_PB + warp;
    const int row0  = gwarp * RPW;

    #pragma unroll
    for (int r = 0; r < RPW; ++r) {
        const float* src = fs + (size_t)(row0 + r) * NODES;
        uint32_t dst = (uint32_t)__cvta_generic_to_shared(&sbuf[r][warp][0]);
        #pragma unroll
        for (int i = 0; i < 8; ++i) {
            const int off = (i * 32 + lane) * 4;
            cp_async16(dst + off * 4, src + off);
        }
        asm volatile("cp.async.commit_group;");
    }

    const int lab0 = labels[row0];
    const int lab1 = labels[row0 + 1];
    float acc = 0.f;

    asm volatile("cp.async.wait_group 1;" ::: "memory");
    __syncwarp();
    if (lane < 28) s_pp[0][warp][lane] = sbuf[0][warp][lane < NC ? lane : lane - NC] * L2E;
    __syncwarp();
    acc  = row_loss(sbuf[0][warp], s_pp[0][warp], lab0, lane);

    asm volatile("cp.async.wait_group 0;" ::: "memory");
    __syncwarp();
    if (lane < 28) s_pp[1][warp][lane] = sbuf[1][warp][lane < NC ? lane : lane - NC] * L2E;
    __syncwarp();
    acc += row_loss(sbuf[1][warp], s_pp[1][warp], lab1, lane);

    if (lane == 0) s_acc[warp] = acc;
    __syncthreads();

    if (threadIdx.x == 0) {
        g_partial[blockIdx.x] = s_acc[0] + s_acc[1] + s_acc[2] + s_acc[3];
        __threadfence();
        s_ticket = atomicAdd(&g_count, 1u);
    }
    __syncthreads();

    if (s_ticket == GRID - 1) {            // deterministic fixed-order final sum
        float s = 0.f;
        #pragma unroll 4
        for (int k = threadIdx.x; k < GRID; k += THREADS) s += g_partial[k];
        s_red[threadIdx.x] = s;
        __syncthreads();
        #pragma unroll
        for (int off = THREADS / 2; off; off >>= 1) {
            if (threadIdx.x < off) s_red[threadIdx.x] += s_red[threadIdx.x + off];
            __syncthreads();
        }
        if (threadIdx.x == 0) {
            out[0] = s_red[0] * (1.0f / (float)BATCH);
            g_count = 0;                   // reset for next graph replay
        }
    }
}

extern "C" void kernel_launch(void* const* d_in, const int* in_sizes, int n_in,
                              void* d_out, int out_size)
{
    const float* fs     = (const float*)d_in[0];
    const int*   labels = (const int*)d_in[1];
    // d_in[2] = stateSpace: compile-time-known structure, unused.
    tree_loss_fused<<<GRID, THREADS>>>(fs, labels, (float*)d_out);
}

// round 4
// speedup vs baseline: 1.4594x; 1.0601x over previous
#include <cuda_runtime.h>
#include <cstdint>

#define BATCH 32768
#define NODES 1024
#define NC 24
#define WARPS_PB 4
#define THREADS (WARPS_PB * 32)   // 128
#define GRID 888                  // 148 SMs * 6 blocks: exactly one wave
#define NW (GRID * WARPS_PB)      // 3552 warps, ~9.2 rows each
#define L2E 1.4426950408889634f
#define LN2 0.6931471805599453f

__device__ float    g_partial[GRID];
__device__ unsigned g_count = 0;  // self-resetting ticket (graph-replay safe)

__device__ __forceinline__ void cp_async16(uint32_t dst_smem, const float* src) {
    asm volatile("cp.async.cg.shared.global [%0], [%1], 16;\n"
                 :: "r"(dst_smem), "l"(src));
}
__device__ __forceinline__ float ex2(float x) {
    float r; asm("ex2.approx.ftz.f32 %0, %1;" : "=f"(r) : "f"(x)); return r;
}
__device__ __forceinline__ float lg2(float x) {
    float r; asm("lg2.approx.ftz.f32 %0, %1;" : "=f"(r) : "f"(x)); return r;
}

// Loss for one row resident in shared `buf` (1024 floats); `pp` = wrap-padded
// parent array: pp[k] = buf[k<24 ? k : k-24] * log2e, k < 28.  (verified R3)
__device__ __forceinline__ float row_loss(const float* __restrict__ buf,
                                          const float* __restrict__ pp,
                                          int label, int lane)
{
    const float4* __restrict__ b4 = reinterpret_cast<const float4*>(buf);
    float4 v[8];
    #pragma unroll
    for (int i = 0; i < 8; ++i) v[i] = b4[i * 32 + lane];   // conflict-free

    int b0 = (4 * lane) % 24;
    int b1 = b0 + 8;  if (b1 >= 24) b1 -= 24;
    int b2 = b1 + 8;  if (b2 >= 24) b2 -= 24;
    float p[3][4];
    #pragma unroll
    for (int j = 0; j < 4; ++j) {
        p[0][j] = pp[b0 + j];
        p[1][j] = pp[b1 + j];
        p[2][j] = pp[b2 + j];
    }

    float z0 = 0.f, z1 = 0.f, z2 = 0.f, z3 = 0.f;
    #pragma unroll
    for (int i = 0; i < 8; ++i) {
        const int pi = i % 3;
        float xv[4] = { v[i].x, v[i].y, v[i].z, v[i].w };
        float t0, t1, t2, t3;
        if (i == 0) {                       // nn = 4*lane+j < 24 for lanes 0..5
            const bool noPar = (lane < 6);
            t0 = ex2(__fmaf_rn(xv[0], L2E, noPar ? 0.f : p[0][0]));
            t1 = ex2(__fmaf_rn(xv[1], L2E, noPar ? 0.f : p[0][1]));
            t2 = ex2(__fmaf_rn(xv[2], L2E, noPar ? 0.f : p[0][2]));
            t3 = ex2(__fmaf_rn(xv[3], L2E, noPar ? 0.f : p[0][3]));
        } else {
            t0 = ex2(__fmaf_rn(xv[0], L2E, p[pi][0]));
            t1 = ex2(__fmaf_rn(xv[1], L2E, p[pi][1]));
            t2 = ex2(__fmaf_rn(xv[2], L2E, p[pi][2]));
            t3 = ex2(__fmaf_rn(xv[3], L2E, p[pi][3]));
        }
        z0 += t0; z1 += t1; z2 += t2; z3 += t3;
    }
    float zsum = (z0 + z1) + (z2 + z3);
    #pragma unroll
    for (int off = 16; off; off >>= 1)
        zsum += __shfl_xor_sync(0xffffffffu, zsum, off);

    float marg;
    if (label < NC) {                       // warp-uniform rare path (~2.3%)
        const int mmax = (1023 - label) / 24;
        float S = 0.f;
        int m = lane + 1;
        if (m <= mmax) S += ex2(buf[label + 24 * m] * L2E);
        m = lane + 33;
        if (m <= mmax) S += ex2(buf[label + 24 * m] * L2E);
        #pragma unroll
        for (int off = 16; off; off >>= 1)
            S += __shfl_xor_sync(0xffffffffu, S, off);
        marg = ex2(pp[label]) * (1.f + S);
    } else {
        marg = ex2(__fmaf_rn(buf[label], L2E, pp[label % NC]));
    }
    return (lg2(1.f + zsum) - lg2(marg)) * LN2;
}

__global__ __launch_bounds__(THREADS) void tree_loss_fused(
    const float* __restrict__ fs, const int* __restrict__ labels,
    float* __restrict__ out)
{
    __shared__ float    sbuf[WARPS_PB][2][NODES];     // 32 KB ring, 2 stages/warp
    __shared__ float    s_pp[WARPS_PB][2][28];
    __shared__ float    s_acc[WARPS_PB];
    __shared__ float    s_red[THREADS];
    __shared__ unsigned s_ticket;

    const int warp  = threadIdx.x >> 5;
    const int lane  = threadIdx.x & 31;
    const int gwarp = blockIdx.x * WARPS_PB + warp;

    // ---- persistent pipelined row loop ----
    int row = gwarp;
    // prologue: stage 0 load
    {
        const float* src = fs + (size_t)row * NODES;  // row < BATCH always (gwarp < NW <= BATCH)
        uint32_t dst = (uint32_t)__cvta_generic_to_shared(&sbuf[warp][0][0]);
        #pragma unroll
        for (int i = 0; i < 8; ++i) {
            const int off = (i * 32 + lane) * 4;
            cp_async16(dst + off * 4, src + off);
        }
    }
    asm volatile("cp.async.commit_group;");

    float acc = 0.f;
    int it = 0;
    while (row < BATCH) {
        const int nrow = row + NW;
        const int s    = it & 1;
        // issue next row's load into the other stage (its compute finished last iter)
        if (nrow < BATCH) {
            const float* src = fs + (size_t)nrow * NODES;
            uint32_t dst = (uint32_t)__cvta_generic_to_shared(&sbuf[warp][s ^ 1][0]);
            #pragma unroll
            for (int i = 0; i < 8; ++i) {
                const int off = (i * 32 + lane) * 4;
                cp_async16(dst + off * 4, src + off);
            }
        }
        asm volatile("cp.async.commit_group;");       // always: keeps group count in lockstep
        asm volatile("cp.async.wait_group 1;" ::: "memory");  // current stage loaded
        __syncwarp();

        if (lane < 28)
            s_pp[warp][s][lane] = sbuf[warp][s][lane < NC ? lane : lane - NC] * L2E;
        __syncwarp();

        const int label = labels[row];                // uniform broadcast load
        acc += row_loss(sbuf[warp][s], s_pp[warp][s], label, lane);

        row = nrow;
        ++it;
    }

    // ---- block sum + deterministic single-pass final reduction ----
    if (lane == 0) s_acc[warp] = acc;
    __syncthreads();

    if (threadIdx.x == 0) {
        g_partial[blockIdx.x] = s_acc[0] + s_acc[1] + s_acc[2] + s_acc[3];
        __threadfence();
        s_ticket = atomicAdd(&g_count, 1u);
    }
    __syncthreads();

    if (s_ticket == GRID - 1) {                        // last block: fixed-order sum
        float s = 0.f;
        #pragma unroll 4
        for (int k = threadIdx.x; k < GRID; k += THREADS) s += g_partial[k];
        s_red[threadIdx.x] = s;
        __syncthreads();
        #pragma unroll
        for (int off = THREADS / 2; off; off >>= 1) {
            if (threadIdx.x < off) s_red[threadIdx.x] += s_red[threadIdx.x + off];
            __syncthreads();
        }
        if (threadIdx.x == 0) {
            out[0] = s_red[0] * (1.0f / (float)BATCH);
            g_count = 0;                               // reset for next replay
        }
    }
}

extern "C" void kernel_launch(void* const* d_in, const int* in_sizes, int n_in,
                              void* d_out, int out_size)
{
    const float* fs     = (const float*)d_in[0];
    const int*   labels = (const int*)d_in[1];
    // d_in[2] = stateSpace: compile-time-known structure, unused.
    tree_loss_fused<<<GRID, THREADS>>>(fs, labels, (float*)d_out);
}